// round 4
// baseline (speedup 1.0000x reference)
#include <cuda_runtime.h>

// VolumeSDFRenderer: R=262144 rays, N=128 samples/ray.
// inputs: distance [R,128] f32, color [R,128,3] f32, depth [R,128] f32
// output: [R,3] f32
//
// NUMERICS (load-bearing): the reference computes tau_i = fl(cumsum_i) - sd_i in fp32,
// with the huge terminal sd_127 = density*1e10 inside the cumsum. At i=127 that is a
// SINGLE rounding of T (~10) against ulp(B): tau_127 = fl(T + B) - B. We reproduce
// exactly that per-element formula: scan EXCLUDES the terminal element (clean excl sum),
// then tau_i = fl(excl_i + sd_i) - sd_i with forced rounding order.

#define SHARP 20.0f
#define NSAMP 128
#define FARD  1e10f

__device__ int g_swap;  // 1 if others[0] is actually depth (values >= 2)

__global__ void classify_kernel(const float* __restrict__ a)
{
    // depth in [2,6); distance ~ N(0,0.1^2)
    float m = 0.0f;
    #pragma unroll
    for (int i = 0; i < 8; i++) m = fmaxf(m, fabsf(a[i]));
    g_swap = (m > 1.0f) ? 1 : 0;
}

__global__ __launch_bounds__(NSAMP, 16)
void volsdf_kernel(const float* __restrict__ inA,
                   const float* __restrict__ inB,
                   const float* __restrict__ color,
                   float* __restrict__ out)
{
    const int swap = g_swap;
    const float* __restrict__ distance = swap ? inB : inA;
    const float* __restrict__ depth    = swap ? inA : inB;

    const int ray  = blockIdx.x;
    const int i    = threadIdx.x;      // sample 0..127
    const int lane = i & 31;
    const int wid  = i >> 5;           // warp 0..3

    __shared__ float s_depth[NSAMP];
    __shared__ float s_wsum[4];
    __shared__ float s_rgb[4][3];

    const size_t base = (size_t)ray * NSAMP;

    // coalesced scalar loads
    float d = distance[base + i];
    float z = depth[base + i];
    s_depth[i] = z;

    const float* crow = color + base * 3;
    float cr = crow[3 * i + 0];
    float cg = crow[3 * i + 1];
    float cb = crow[3 * i + 2];

    __syncthreads();

    // forward-difference delta, huge terminal delta
    float delta = (i < NSAMP - 1) ? (s_depth[i + 1] - z) : FARD;

    // density = S*e/(1+e)^2
    float e   = __expf(-SHARP * d);
    float op  = 1.0f + e;
    float den = SHARP * e / (op * op);
    float sd  = den * delta;

    // ---- exclusive scan of sd with the terminal (huge) element EXCLUDED ----
    float sdz = (i == NSAMP - 1) ? 0.0f : sd;
    float incl = sdz;
    #pragma unroll
    for (int off = 1; off < 32; off <<= 1) {
        float v = __shfl_up_sync(0xffffffffu, incl, off);
        if (lane >= off) incl += v;
    }
    if (lane == 31) s_wsum[wid] = incl;
    __syncthreads();

    float wbase = 0.0f;
    #pragma unroll
    for (int w = 0; w < 4; w++) {
        float t = s_wsum[w];
        if (w < wid) wbase += t;
    }
    float excl = (wbase + incl) - sdz;   // clean exclusive cumsum (no huge term)

    // ---- reference's per-element rounding: tau = fl(excl + sd) - sd ----
    // At i=127 this is the single quantization fl(T + B) - B the reference performs.
    float csum = __fadd_rn(excl, sd);
    float tau  = __fsub_rn(csum, sd);

    float weight = __expf(-tau) * (1.0f - __expf(-sd));

    // weighted rgb, block reduction
    float fr = weight * cr;
    float fg = weight * cg;
    float fb = weight * cb;
    #pragma unroll
    for (int off = 16; off > 0; off >>= 1) {
        fr += __shfl_xor_sync(0xffffffffu, fr, off);
        fg += __shfl_xor_sync(0xffffffffu, fg, off);
        fb += __shfl_xor_sync(0xffffffffu, fb, off);
    }
    if (lane == 0) {
        s_rgb[wid][0] = fr;
        s_rgb[wid][1] = fg;
        s_rgb[wid][2] = fb;
    }
    __syncthreads();

    if (i == 0) {
        float r = s_rgb[0][0] + s_rgb[1][0] + s_rgb[2][0] + s_rgb[3][0];
        float g = s_rgb[0][1] + s_rgb[1][1] + s_rgb[2][1] + s_rgb[3][1];
        float b = s_rgb[0][2] + s_rgb[1][2] + s_rgb[2][2] + s_rgb[3][2];
        float* o = out + (size_t)ray * 3;
        o[0] = fminf(fmaxf(r, 0.0f), 1.0f);
        o[1] = fminf(fmaxf(g, 0.0f), 1.0f);
        o[2] = fminf(fmaxf(b, 0.0f), 1.0f);
    }
}

extern "C" void kernel_launch(void* const* d_in, const int* in_sizes, int n_in,
                              void* d_out, int out_size)
{
    // color = input with the largest element count (R*N*3)
    int ci = 0;
    for (int k = 1; k < n_in; k++)
        if (in_sizes[k] > in_sizes[ci]) ci = k;

    int others[2], no = 0;
    for (int k = 0; k < n_in && no < 2; k++)
        if (k != ci) others[no++] = k;

    const float* inA   = (const float*)d_in[others[0]];
    const float* inB   = (const float*)d_in[others[1]];
    const float* color = (const float*)d_in[ci];
    float* out = (float*)d_out;

    const int R = in_sizes[ci] / (NSAMP * 3);   // 262144

    classify_kernel<<<1, 1>>>(inA);
    volsdf_kernel<<<R, NSAMP>>>(inA, inB, color, out);
}

// round 5
// speedup vs baseline: 1.8281x; 1.8281x over previous
#include <cuda_runtime.h>

// VolumeSDFRenderer: R=262144 rays, N=128 samples/ray.
// inputs: distance [R,128] f32, color [R,128,3] f32, depth [R,128] f32
// output: [R,3] f32
//
// Warp per ray; lane l owns samples 4l..4l+3. All loads are float4 (LDG.128,
// fully coalesced). No shared memory, no block barriers.
//
// NUMERICS (load-bearing, from R3/R4 analysis): the reference computes
// tau_i = fl(fp32_cumsum(sd)_i) - sd_i with the huge terminal
// sd_127 = density*1e10 INSIDE the cumsum; at i=127 that collapses to the single
// quantization fl(T + B) - B ~= 0, so the terminal sample gets weight ~= 1.
// We exclude B from the scan (clean exclusive sum) and then apply the reference's
// per-element rounding tau = fl(excl + sd) - sd with forced rounding order.
// Weights use the literal formula exp(-tau) * (1 - exp(-sd)) (no telescoping).

#define SHARP 20.0f
#define NSAMP 128
#define FARD  1e10f

__device__ int g_swap;  // 1 if inA is actually depth (values >= 2)

__global__ void classify_kernel(const float* __restrict__ a)
{
    float m = 0.0f;
    #pragma unroll
    for (int i = 0; i < 8; i++) m = fmaxf(m, fabsf(a[i]));
    g_swap = (m > 1.0f) ? 1 : 0;
}

__device__ __forceinline__ float sample_weight(float excl, float sd)
{
    // reference per-element rounding: tau = fl(excl + sd) - sd
    float csum = __fadd_rn(excl, sd);
    float tau  = __fsub_rn(csum, sd);
    return __expf(-tau) * (1.0f - __expf(-sd));
}

__global__ __launch_bounds__(256, 8)
void volsdf_kernel(const float* __restrict__ inA,
                   const float* __restrict__ inB,
                   const float* __restrict__ color,
                   float* __restrict__ out,
                   int R)
{
    const int swap = g_swap;
    const float* __restrict__ distance = swap ? inB : inA;
    const float* __restrict__ depth    = swap ? inA : inB;

    const int warp_id = (blockIdx.x * blockDim.x + threadIdx.x) >> 5;
    const int lane    = threadIdx.x & 31;
    if (warp_id >= R) return;
    const int ray = warp_id;

    // ---- coalesced float4 loads: 5 independent LDG.128 per lane ----
    const float4* dist4 = reinterpret_cast<const float4*>(distance + (size_t)ray * NSAMP);
    const float4* dep4  = reinterpret_cast<const float4*>(depth    + (size_t)ray * NSAMP);
    const float4* col4  = reinterpret_cast<const float4*>(color    + (size_t)ray * NSAMP * 3);

    float4 dv = dist4[lane];
    float4 zv = dep4[lane];
    float4 c0 = col4[lane * 3 + 0];   // r0 g0 b0 r1
    float4 c1 = col4[lane * 3 + 1];   // g1 b1 r2 g2
    float4 c2 = col4[lane * 3 + 2];   // b2 r3 g3 b3

    // ---- deltas: next lane's first depth for the chunk-boundary diff ----
    float znext = __shfl_down_sync(0xffffffffu, zv.x, 1);
    float dl0 = zv.y - zv.x;
    float dl1 = zv.z - zv.y;
    float dl2 = zv.w - zv.z;
    float dl3 = (lane == 31) ? FARD : (znext - zv.w);

    // ---- sd = density * delta ----
    float e, op;
    e = __expf(-SHARP * dv.x); op = 1.0f + e; float sd0 = (SHARP * e / (op * op)) * dl0;
    e = __expf(-SHARP * dv.y); op = 1.0f + e; float sd1 = (SHARP * e / (op * op)) * dl1;
    e = __expf(-SHARP * dv.z); op = 1.0f + e; float sd2 = (SHARP * e / (op * op)) * dl2;
    e = __expf(-SHARP * dv.w); op = 1.0f + e; float sd3 = (SHARP * e / (op * op)) * dl3;

    // ---- exclusive scan, EXCLUDING the huge terminal element ----
    float sdz3 = (lane == 31) ? 0.0f : sd3;
    float q0 = sd0;
    float q1 = q0 + sd1;
    float q2 = q1 + sd2;
    float q3 = q2 + sdz3;            // lane total (terminal excluded)

    float incl = q3;
    #pragma unroll
    for (int off = 1; off < 32; off <<= 1) {
        float v = __shfl_up_sync(0xffffffffu, incl, off);
        if (lane >= off) incl += v;
    }
    float base = incl - q3;          // exclusive prefix entering this lane

    // ---- weights: literal reference formula, per-element rounding ----
    float w0 = sample_weight(base,      sd0);
    float w1 = sample_weight(base + q0, sd1);
    float w2 = sample_weight(base + q1, sd2);
    float w3 = sample_weight(base + q2, sd3);  // lane31: fl(T+B)-B cancellation

    // ---- weighted RGB ----
    float fr = w0 * c0.x + w1 * c0.w + w2 * c1.z + w3 * c2.y;
    float fg = w0 * c0.y + w1 * c1.x + w2 * c1.w + w3 * c2.z;
    float fb = w0 * c0.z + w1 * c1.y + w2 * c2.x + w3 * c2.w;

    // ---- warp reduce ----
    #pragma unroll
    for (int off = 16; off > 0; off >>= 1) {
        fr += __shfl_xor_sync(0xffffffffu, fr, off);
        fg += __shfl_xor_sync(0xffffffffu, fg, off);
        fb += __shfl_xor_sync(0xffffffffu, fb, off);
    }

    // lanes 0..2 write one component each (all lanes hold the full sums)
    if (lane < 3) {
        float v = (lane == 0) ? fr : (lane == 1) ? fg : fb;
        out[(size_t)ray * 3 + lane] = fminf(fmaxf(v, 0.0f), 1.0f);
    }
}

extern "C" void kernel_launch(void* const* d_in, const int* in_sizes, int n_in,
                              void* d_out, int out_size)
{
    // color = input with the largest element count (R*N*3)
    int ci = 0;
    for (int k = 1; k < n_in; k++)
        if (in_sizes[k] > in_sizes[ci]) ci = k;

    int others[2], no = 0;
    for (int k = 0; k < n_in && no < 2; k++)
        if (k != ci) others[no++] = k;

    const float* inA   = (const float*)d_in[others[0]];
    const float* inB   = (const float*)d_in[others[1]];
    const float* color = (const float*)d_in[ci];
    float* out = (float*)d_out;

    const int R = in_sizes[ci] / (NSAMP * 3);   // 262144

    classify_kernel<<<1, 1>>>(inA);
    int blocks = (R + 7) / 8;                    // 8 warps (rays) per 256-thread block
    volsdf_kernel<<<blocks, 256>>>(inA, inB, color, out, R);
}

// round 6
// speedup vs baseline: 1.8848x; 1.0310x over previous
#include <cuda_runtime.h>

// VolumeSDFRenderer: R=262144 rays, N=128 samples/ray.
// inputs (metadata order): distance [R,128] f32, color [R,128,3] f32, depth [R,128] f32
// output: [R,3] f32
//
// Warp per ray; lane l owns samples 4l..4l+3. All loads are float4 LDG.128,
// fully coalesced, with streaming (.cs) hints since every byte is read once.
// No shared memory, no block barriers. Single kernel launch (input mapping
// proven by the R2 error-signature experiment: metadata order holds; color
// identified structurally by its 3x element count).
//
// NUMERICS (load-bearing): the reference computes tau_i = fl(cumsum(sd)_i) - sd_i
// in fp32 with the huge terminal sd_127 = density*1e10 INSIDE the cumsum; at
// i=127 this collapses to the single quantization fl(T + B) - B ~= 0 giving the
// terminal sample weight ~= 1. We exclude B from the scan (clean exclusive sum)
// and apply the reference's per-element rounding tau = fl(excl + sd) - sd with
// explicit __fadd_rn/__fsub_rn. Weights use the literal formula
// exp(-tau) * (1 - exp(-sd)); no telescoping.

#define SHARP 20.0f
#define NSAMP 128
#define FARD  1e10f

__device__ __forceinline__ float sample_weight(float excl, float sd)
{
    float csum = __fadd_rn(excl, sd);
    float tau  = __fsub_rn(csum, sd);
    return __expf(-tau) * (1.0f - __expf(-sd));
}

__global__ __launch_bounds__(256, 8)
void volsdf_kernel(const float* __restrict__ distance,
                   const float* __restrict__ color,
                   const float* __restrict__ depth,
                   float* __restrict__ out,
                   int R)
{
    const int warp_id = (blockIdx.x * blockDim.x + threadIdx.x) >> 5;
    const int lane    = threadIdx.x & 31;
    if (warp_id >= R) return;
    const int ray = warp_id;

    // ---- coalesced float4 streaming loads: 5 independent LDG.128 per lane ----
    const float4* dist4 = reinterpret_cast<const float4*>(distance + (size_t)ray * NSAMP);
    const float4* dep4  = reinterpret_cast<const float4*>(depth    + (size_t)ray * NSAMP);
    const float4* col4  = reinterpret_cast<const float4*>(color    + (size_t)ray * NSAMP * 3);

    float4 dv = __ldcs(&dist4[lane]);
    float4 zv = __ldcs(&dep4[lane]);
    float4 c0 = __ldcs(&col4[lane * 3 + 0]);   // r0 g0 b0 r1
    float4 c1 = __ldcs(&col4[lane * 3 + 1]);   // g1 b1 r2 g2
    float4 c2 = __ldcs(&col4[lane * 3 + 2]);   // b2 r3 g3 b3

    // ---- deltas: next lane's first depth closes this lane's chunk ----
    float znext = __shfl_down_sync(0xffffffffu, zv.x, 1);
    float dl0 = zv.y - zv.x;
    float dl1 = zv.z - zv.y;
    float dl2 = zv.w - zv.z;
    float dl3 = (lane == 31) ? FARD : (znext - zv.w);

    // ---- sd = density * delta,  density = S*e/(1+e)^2 ----
    float e, op;
    e = __expf(-SHARP * dv.x); op = 1.0f + e; float sd0 = (SHARP * e / (op * op)) * dl0;
    e = __expf(-SHARP * dv.y); op = 1.0f + e; float sd1 = (SHARP * e / (op * op)) * dl1;
    e = __expf(-SHARP * dv.z); op = 1.0f + e; float sd2 = (SHARP * e / (op * op)) * dl2;
    e = __expf(-SHARP * dv.w); op = 1.0f + e; float sd3 = (SHARP * e / (op * op)) * dl3;

    // ---- exclusive scan, EXCLUDING the huge terminal element ----
    float sdz3 = (lane == 31) ? 0.0f : sd3;
    float q0 = sd0;
    float q1 = q0 + sd1;
    float q2 = q1 + sd2;
    float q3 = q2 + sdz3;            // lane total (terminal excluded)

    float incl = q3;
    #pragma unroll
    for (int off = 1; off < 32; off <<= 1) {
        float v = __shfl_up_sync(0xffffffffu, incl, off);
        if (lane >= off) incl += v;
    }
    float base = incl - q3;          // exclusive prefix entering this lane

    // ---- weights: literal reference formula, per-element rounding ----
    float w0 = sample_weight(base,      sd0);
    float w1 = sample_weight(base + q0, sd1);
    float w2 = sample_weight(base + q1, sd2);
    float w3 = sample_weight(base + q2, sd3);  // lane31: fl(T+B)-B cancellation

    // ---- weighted RGB ----
    float fr = w0 * c0.x + w1 * c0.w + w2 * c1.z + w3 * c2.y;
    float fg = w0 * c0.y + w1 * c1.x + w2 * c1.w + w3 * c2.z;
    float fb = w0 * c0.z + w1 * c1.y + w2 * c2.x + w3 * c2.w;

    // ---- warp reduce ----
    #pragma unroll
    for (int off = 16; off > 0; off >>= 1) {
        fr += __shfl_xor_sync(0xffffffffu, fr, off);
        fg += __shfl_xor_sync(0xffffffffu, fg, off);
        fb += __shfl_xor_sync(0xffffffffu, fb, off);
    }

    // lanes 0..2 write one component each (all lanes hold the full sums)
    if (lane < 3) {
        float v = (lane == 0) ? fr : (lane == 1) ? fg : fb;
        __stcs(&out[(size_t)ray * 3 + lane], fminf(fmaxf(v, 0.0f), 1.0f));
    }
}

extern "C" void kernel_launch(void* const* d_in, const int* in_sizes, int n_in,
                              void* d_out, int out_size)
{
    // color = input with the largest element count (R*N*3); the remaining two
    // follow metadata order: distance first, depth second (mapping confirmed by
    // the R2 error-signature experiment).
    int ci = 0;
    for (int k = 1; k < n_in; k++)
        if (in_sizes[k] > in_sizes[ci]) ci = k;

    int others[2], no = 0;
    for (int k = 0; k < n_in && no < 2; k++)
        if (k != ci) others[no++] = k;

    const float* distance = (const float*)d_in[others[0]];
    const float* color    = (const float*)d_in[ci];
    const float* depth    = (const float*)d_in[others[1]];
    float* out = (float*)d_out;

    const int R = in_sizes[ci] / (NSAMP * 3);   // 262144

    int blocks = (R + 7) / 8;                   // 8 warps (rays) per 256-thread block
    volsdf_kernel<<<blocks, 256>>>(distance, color, depth, out, R);
}

// round 7
// speedup vs baseline: 1.8886x; 1.0020x over previous
#include <cuda_runtime.h>

// VolumeSDFRenderer: R=262144 rays, N=128 samples/ray.  FINAL (converged).
// inputs (metadata order): distance [R,128] f32, color [R,128,3] f32, depth [R,128] f32
// output: [R,3] f32
//
// Warp per ray; lane l owns samples 4l..4l+3. Five float4 LDG.128 per lane,
// fully coalesced, streaming hints. No shared memory, no block barriers,
// single launch. Measured 6.92 TB/s = the B300 LTS chip cap (~6300 B/cyc,
// path-independent) on 674 MB of compulsory traffic -> ~97 us is the floor.
//
// NUMERICS (load-bearing): the reference computes tau_i = fl(cumsum(sd)_i) - sd_i
// in fp32 with the huge terminal sd_127 = density*1e10 INSIDE the cumsum; at
// i=127 this collapses to the single quantization fl(T + B) - B ~= 0 giving the
// terminal sample weight ~= 1. We exclude B from the scan (clean exclusive sum)
// and apply the reference's per-element rounding tau = fl(excl + sd) - sd with
// explicit __fadd_rn/__fsub_rn. Weights use the literal formula
// exp(-tau) * (1 - exp(-sd)); no telescoping.

#define SHARP 20.0f
#define NSAMP 128
#define FARD  1e10f

__device__ __forceinline__ float sample_weight(float excl, float sd)
{
    float csum = __fadd_rn(excl, sd);
    float tau  = __fsub_rn(csum, sd);
    return __expf(-tau) * (1.0f - __expf(-sd));
}

__global__ __launch_bounds__(256, 8)
void volsdf_kernel(const float* __restrict__ distance,
                   const float* __restrict__ color,
                   const float* __restrict__ depth,
                   float* __restrict__ out,
                   int R)
{
    const int warp_id = (blockIdx.x * blockDim.x + threadIdx.x) >> 5;
    const int lane    = threadIdx.x & 31;
    if (warp_id >= R) return;
    const int ray = warp_id;

    // ---- coalesced float4 streaming loads: 5 independent LDG.128 per lane ----
    const float4* dist4 = reinterpret_cast<const float4*>(distance + (size_t)ray * NSAMP);
    const float4* dep4  = reinterpret_cast<const float4*>(depth    + (size_t)ray * NSAMP);
    const float4* col4  = reinterpret_cast<const float4*>(color    + (size_t)ray * NSAMP * 3);

    float4 dv = __ldcs(&dist4[lane]);
    float4 zv = __ldcs(&dep4[lane]);
    float4 c0 = __ldcs(&col4[lane * 3 + 0]);   // r0 g0 b0 r1
    float4 c1 = __ldcs(&col4[lane * 3 + 1]);   // g1 b1 r2 g2
    float4 c2 = __ldcs(&col4[lane * 3 + 2]);   // b2 r3 g3 b3

    // ---- deltas: next lane's first depth closes this lane's chunk ----
    float znext = __shfl_down_sync(0xffffffffu, zv.x, 1);
    float dl0 = zv.y - zv.x;
    float dl1 = zv.z - zv.y;
    float dl2 = zv.w - zv.z;
    float dl3 = (lane == 31) ? FARD : (znext - zv.w);

    // ---- sd = density * delta,  density = S*e/(1+e)^2 ----
    float e, op;
    e = __expf(-SHARP * dv.x); op = 1.0f + e; float sd0 = (SHARP * e / (op * op)) * dl0;
    e = __expf(-SHARP * dv.y); op = 1.0f + e; float sd1 = (SHARP * e / (op * op)) * dl1;
    e = __expf(-SHARP * dv.z); op = 1.0f + e; float sd2 = (SHARP * e / (op * op)) * dl2;
    e = __expf(-SHARP * dv.w); op = 1.0f + e; float sd3 = (SHARP * e / (op * op)) * dl3;

    // ---- exclusive scan, EXCLUDING the huge terminal element ----
    float sdz3 = (lane == 31) ? 0.0f : sd3;
    float q0 = sd0;
    float q1 = q0 + sd1;
    float q2 = q1 + sd2;
    float q3 = q2 + sdz3;            // lane total (terminal excluded)

    float incl = q3;
    #pragma unroll
    for (int off = 1; off < 32; off <<= 1) {
        float v = __shfl_up_sync(0xffffffffu, incl, off);
        if (lane >= off) incl += v;
    }
    float base = incl - q3;          // exclusive prefix entering this lane

    // ---- weights: literal reference formula, per-element rounding ----
    float w0 = sample_weight(base,      sd0);
    float w1 = sample_weight(base + q0, sd1);
    float w2 = sample_weight(base + q1, sd2);
    float w3 = sample_weight(base + q2, sd3);  // lane31: fl(T+B)-B cancellation

    // ---- weighted RGB ----
    float fr = w0 * c0.x + w1 * c0.w + w2 * c1.z + w3 * c2.y;
    float fg = w0 * c0.y + w1 * c1.x + w2 * c1.w + w3 * c2.z;
    float fb = w0 * c0.z + w1 * c1.y + w2 * c2.x + w3 * c2.w;

    // ---- warp reduce ----
    #pragma unroll
    for (int off = 16; off > 0; off >>= 1) {
        fr += __shfl_xor_sync(0xffffffffu, fr, off);
        fg += __shfl_xor_sync(0xffffffffu, fg, off);
        fb += __shfl_xor_sync(0xffffffffu, fb, off);
    }

    // lanes 0..2 write one component each (all lanes hold the full sums)
    if (lane < 3) {
        float v = (lane == 0) ? fr : (lane == 1) ? fg : fb;
        __stcs(&out[(size_t)ray * 3 + lane], fminf(fmaxf(v, 0.0f), 1.0f));
    }
}

extern "C" void kernel_launch(void* const* d_in, const int* in_sizes, int n_in,
                              void* d_out, int out_size)
{
    // color = input with the largest element count (R*N*3); the remaining two
    // follow metadata order: distance first, depth second (mapping confirmed by
    // the R2 error-signature experiment).
    int ci = 0;
    for (int k = 1; k < n_in; k++)
        if (in_sizes[k] > in_sizes[ci]) ci = k;

    int others[2], no = 0;
    for (int k = 0; k < n_in && no < 2; k++)
        if (k != ci) others[no++] = k;

    const float* distance = (const float*)d_in[others[0]];
    const float* color    = (const float*)d_in[ci];
    const float* depth    = (const float*)d_in[others[1]];
    float* out = (float*)d_out;

    const int R = in_sizes[ci] / (NSAMP * 3);   // 262144

    int blocks = (R + 7) / 8;                   // 8 warps (rays) per 256-thread block
    volsdf_kernel<<<blocks, 256>>>(distance, color, depth, out, R);
}